// round 1
// baseline (speedup 1.0000x reference)
#include <cuda_runtime.h>
#include <math_constants.h>

// Problem shape (fixed per reference)
constexpr int Bb = 4;
constexpr int Ss = 2048;
constexpr int Dd = 1024;

// Scratch (static __device__ allocation is allowed; no cudaMalloc anywhere)
__device__ float g_q  [(long long)Bb * Ss * Dd];  // 32 MB
__device__ float g_k  [(long long)Bb * Ss * Dd];  // 32 MB
__device__ float g_v  [(long long)Bb * Ss * Dd];  // 32 MB
__device__ float g_ctx[(long long)Bb * Ss * Dd];  // 32 MB
__device__ float g_att[(long long)Bb * Ss * Ss];  // 64 MB (scores -> attn in place)

// ---------------------------------------------------------------------------
// SIMT SGEMM: C[M,N] = A[M,K] * B  (B either [K,N] row-major, or, if BT,
// [N,K] row-major so C = A * B^T). 128x128 tile, BK=16, 256 threads,
// 8x8 per-thread fragments split as (4 + 4) with a 64-offset to keep
// shared-memory reads conflict-free.
//   CSKIP : causal tile skip (scores GEMM) — blocks with col0 > row0+127 exit.
//   KLIM  : limit K loop to row0+128 (ctx GEMM; attn is exactly zero beyond).
//   BIAS  : add bias[col] at epilogue (output projection).
// All dims must be multiples of 128 (they are: 1024/2048/8192).
// ---------------------------------------------------------------------------
#define GBM 128
#define GBN 128
#define GBK 16

template <bool BT, bool CSKIP, bool KLIM, bool BIAS>
__global__ void __launch_bounds__(256, 2)
sgemm_kernel(const float* __restrict__ A, const float* __restrict__ B,
             const float* __restrict__ bias, float* __restrict__ C,
             int M, int N, int K,
             long long strA, long long strB, long long strC)
{
    const int row0 = blockIdx.y * GBM;
    const int col0 = blockIdx.x * GBN;
    if (CSKIP && col0 > row0 + GBM - 1) return;   // fully-masked causal block

    int Keff = K;
    if (KLIM) { int lim = row0 + GBM; Keff = lim < K ? lim : K; }

    const long long bz = blockIdx.z;
    A += bz * strA;
    B += bz * strB;
    C += bz * strC;

    __shared__ float As[GBK][GBM + 4];
    __shared__ float Bs[GBK][GBN + 4];

    const int tid  = threadIdx.x;
    const int tx   = tid & 15;    // 16 cols of threads
    const int ty   = tid >> 4;    // 16 rows of threads

    // A-tile (and NT B-tile) loader mapping: 128 rows x 16 cols, float4
    const int ldRow  = tid >> 2;          // 0..63 (two passes of 64 rows)
    const int ldCol4 = (tid & 3) << 2;    // 0,4,8,12

    float acc[8][8];
#pragma unroll
    for (int i = 0; i < 8; i++)
#pragma unroll
        for (int j = 0; j < 8; j++) acc[i][j] = 0.f;

    for (int k0 = 0; k0 < Keff; k0 += GBK) {
        // ---- load A tile (transpose into smem) ----
#pragma unroll
        for (int p = 0; p < 2; p++) {
            int r = ldRow + p * 64;
            float4 v = *reinterpret_cast<const float4*>(
                &A[(long long)(row0 + r) * K + k0 + ldCol4]);
            As[ldCol4 + 0][r] = v.x;
            As[ldCol4 + 1][r] = v.y;
            As[ldCol4 + 2][r] = v.z;
            As[ldCol4 + 3][r] = v.w;
        }
        // ---- load B tile ----
        if (BT) {
            // B is [N,K] row-major; need Bs[k][n] = B[col0+n][k0+k]
#pragma unroll
            for (int p = 0; p < 2; p++) {
                int r = ldRow + p * 64;   // n index
                float4 v = *reinterpret_cast<const float4*>(
                    &B[(long long)(col0 + r) * K + k0 + ldCol4]);
                Bs[ldCol4 + 0][r] = v.x;
                Bs[ldCol4 + 1][r] = v.y;
                Bs[ldCol4 + 2][r] = v.z;
                Bs[ldCol4 + 3][r] = v.w;
            }
        } else {
            // B is [K,N] row-major; 16 rows x 128 cols
            const int bRow  = tid >> 5;          // 0..7 (two passes of 8 rows)
            const int bCol4 = (tid & 31) << 2;   // 0..124
#pragma unroll
            for (int p = 0; p < 2; p++) {
                int r = bRow + p * 8;
                float4 v = *reinterpret_cast<const float4*>(
                    &B[(long long)(k0 + r) * N + col0 + bCol4]);
                *reinterpret_cast<float4*>(&Bs[r][bCol4]) = v;
            }
        }
        __syncthreads();

        // ---- compute ----
#pragma unroll
        for (int kk = 0; kk < GBK; kk++) {
            float a[8], b[8];
            float4 a0 = *reinterpret_cast<const float4*>(&As[kk][ty * 4]);
            float4 a1 = *reinterpret_cast<const float4*>(&As[kk][64 + ty * 4]);
            float4 b0 = *reinterpret_cast<const float4*>(&Bs[kk][tx * 4]);
            float4 b1 = *reinterpret_cast<const float4*>(&Bs[kk][64 + tx * 4]);
            a[0]=a0.x; a[1]=a0.y; a[2]=a0.z; a[3]=a0.w;
            a[4]=a1.x; a[5]=a1.y; a[6]=a1.z; a[7]=a1.w;
            b[0]=b0.x; b[1]=b0.y; b[2]=b0.z; b[3]=b0.w;
            b[4]=b1.x; b[5]=b1.y; b[6]=b1.z; b[7]=b1.w;
#pragma unroll
            for (int i = 0; i < 8; i++)
#pragma unroll
                for (int j = 0; j < 8; j++)
                    acc[i][j] = fmaf(a[i], b[j], acc[i][j]);
        }
        __syncthreads();
    }

    // ---- epilogue ----
#pragma unroll
    for (int i = 0; i < 8; i++) {
        int r = row0 + (i < 4 ? ty * 4 + i : 64 + ty * 4 + (i - 4));
#pragma unroll
        for (int half = 0; half < 2; half++) {
            int c = col0 + (half == 0 ? tx * 4 : 64 + tx * 4);
            float4 v;
            v.x = acc[i][half * 4 + 0];
            v.y = acc[i][half * 4 + 1];
            v.z = acc[i][half * 4 + 2];
            v.w = acc[i][half * 4 + 3];
            if (BIAS) {
                v.x += bias[c + 0];
                v.y += bias[c + 1];
                v.z += bias[c + 2];
                v.w += bias[c + 3];
            }
            *reinterpret_cast<float4*>(&C[(long long)r * N + c]) = v;
        }
    }
}

// ---------------------------------------------------------------------------
// Causal softmax in place on g_att. One block per (q, b) row.
// attn[q][j] = softmax_j(scores[q][j] / 32) for j <= q, and exact 0 for
// q < j < roundup128(q+1) so the K-limited ctx GEMM reads only valid data.
// ---------------------------------------------------------------------------
__global__ void __launch_bounds__(256)
softmax_kernel(float* __restrict__ att)
{
    const int q = blockIdx.x;
    const int b = blockIdx.y;
    float* row = att + ((long long)b * Ss + q) * (long long)Ss;
    const int n = q + 1;
    const float scale = 0.03125f;   // 1/sqrt(1024)
    const int tid = threadIdx.x;

    __shared__ float sred[8];

    // pass 1: max of scaled scores
    float m = -CUDART_INF_F;
    for (int j = tid; j < n; j += 256) m = fmaxf(m, row[j] * scale);
#pragma unroll
    for (int o = 16; o; o >>= 1) m = fmaxf(m, __shfl_xor_sync(0xffffffffu, m, o));
    if ((tid & 31) == 0) sred[tid >> 5] = m;
    __syncthreads();
    if (tid == 0) {
        float v = sred[0];
#pragma unroll
        for (int w = 1; w < 8; w++) v = fmaxf(v, sred[w]);
        sred[0] = v;
    }
    __syncthreads();
    m = sred[0];
    __syncthreads();

    // pass 2: exp + sum (values kept in registers; <=8 per thread)
    float ev[8];
    float s = 0.f;
    int cnt = 0;
    for (int j = tid; j < n; j += 256) {
        float e = __expf(row[j] * scale - m);
        ev[cnt++] = e;
        s += e;
    }
#pragma unroll
    for (int o = 16; o; o >>= 1) s += __shfl_xor_sync(0xffffffffu, s, o);
    if ((tid & 31) == 0) sred[tid >> 5] = s;
    __syncthreads();
    if (tid == 0) {
        float v = sred[0];
#pragma unroll
        for (int w = 1; w < 8; w++) v += sred[w];
        sred[0] = v;
    }
    __syncthreads();
    const float inv = 1.f / sred[0];

    // write normalized probs
    cnt = 0;
    for (int j = tid; j < n; j += 256) row[j] = ev[cnt++] * inv;

    // zero the masked tail inside this row's own 128-block
    const int jend = ((q >> 7) + 1) << 7;
    for (int j = n + tid; j < jend; j += 256) row[j] = 0.f;
}

// ---------------------------------------------------------------------------
extern "C" void kernel_launch(void* const* d_in, const int* in_sizes, int n_in,
                              void* d_out, int out_size)
{
    const float* inp = (const float*)d_in[0];
    const float* Wq  = (const float*)d_in[1];
    const float* Wk  = (const float*)d_in[2];
    const float* Wv  = (const float*)d_in[3];
    const float* Wo  = (const float*)d_in[4];
    const float* bo  = (const float*)d_in[5];
    float* out = (float*)d_out;

    float *q, *k, *v, *ctx, *att;
    cudaGetSymbolAddress((void**)&q,   g_q);
    cudaGetSymbolAddress((void**)&k,   g_k);
    cudaGetSymbolAddress((void**)&v,   g_v);
    cudaGetSymbolAddress((void**)&ctx, g_ctx);
    cudaGetSymbolAddress((void**)&att, g_att);

    const int M  = Bb * Ss;                 // 8192
    const long long sQK = (long long)Ss * Dd;   // per-batch q/k/v stride
    const long long sAT = (long long)Ss * Ss;   // per-batch attn stride

    dim3 blk(256);

    // 1) Q/K/V projections: [8192,1024] x [1024,1024]
    {
        dim3 grid(Dd / GBN, M / GBM, 1);
        sgemm_kernel<false,false,false,false><<<grid, blk>>>(inp, Wq, nullptr, q,  M, Dd, Dd, 0, 0, 0);
        sgemm_kernel<false,false,false,false><<<grid, blk>>>(inp, Wk, nullptr, k,  M, Dd, Dd, 0, 0, 0);
        sgemm_kernel<false,false,false,false><<<grid, blk>>>(inp, Wv, nullptr, v,  M, Dd, Dd, 0, 0, 0);
    }

    // 2) scores = Q * K^T per batch (causal tile skip)
    {
        dim3 grid(Ss / GBN, Ss / GBM, Bb);
        sgemm_kernel<true,true,false,false><<<grid, blk>>>(q, k, nullptr, att, Ss, Ss, Dd, sQK, sQK, sAT);
    }

    // 3) causal softmax (mask, /32, normalize, zero-fill tail)
    {
        dim3 grid(Ss, Bb);
        softmax_kernel<<<grid, blk>>>(att);
    }

    // 4) ctx = attn * V per batch (K loop limited to row0+128)
    {
        dim3 grid(Dd / GBN, Ss / GBM, Bb);
        sgemm_kernel<false,false,true,false><<<grid, blk>>>(att, v, nullptr, ctx, Ss, Dd, Ss, sAT, sQK, sQK);
    }

    // 5) out = ctx * W_o + b_o
    {
        dim3 grid(Dd / GBN, M / GBM, 1);
        sgemm_kernel<false,false,false,true><<<grid, blk>>>(ctx, Wo, bo, out, M, Dd, Dd, 0, 0, 0);
    }
}

// round 4
// speedup vs baseline: 3.7684x; 3.7684x over previous
#include <cuda_runtime.h>
#include <cuda_fp16.h>
#include <cuda_pipeline.h>
#include <math_constants.h>
#include <mma.h>

using namespace nvcuda;

// Problem shape (fixed per reference)
constexpr int Bb = 4;
constexpr int Ss = 2048;
constexpr int Dd = 1024;
constexpr long long QKV_E = (long long)Bb * Ss * Dd;   // 8,388,608
constexpr long long ATT_E = (long long)Bb * Ss * Ss;   // 16,777,216

// ---- static scratch (no cudaMalloc anywhere) ----
// fp16 operands
__device__ __half g_inp_h[QKV_E];
__device__ __half g_wq_t[(long long)Dd * Dd];
__device__ __half g_wk_t[(long long)Dd * Dd];
__device__ __half g_wv_t[(long long)Dd * Dd];
__device__ __half g_wo_t[(long long)Dd * Dd];
__device__ __half g_q_h [QKV_E];
__device__ __half g_k_h [QKV_E];
__device__ __half g_vT_h[QKV_E];
__device__ __half g_att_h[ATT_E];
__device__ __half g_ctx_h[QKV_E];
// fp32 GEMM outputs
__device__ float g_q_f  [QKV_E];
__device__ float g_k_f  [QKV_E];
__device__ float g_v_f  [QKV_E];
__device__ float g_ctx_f[QKV_E];
__device__ float g_att_f[ATT_E];

// device-side buffer selectors (avoids any host symbol lookup)
__device__ __forceinline__ __half* hbuf(int id)
{
    switch (id) {
        case 0: return g_inp_h;
        case 1: return g_wq_t;
        case 2: return g_wk_t;
        case 3: return g_wv_t;
        case 4: return g_wo_t;
        case 5: return g_q_h;
        case 6: return g_k_h;
        case 7: return g_vT_h;
        case 8: return g_att_h;
        default: return g_ctx_h;
    }
}

__device__ __forceinline__ float* fbuf(int id)
{
    switch (id) {
        case 0: return g_q_f;
        case 1: return g_k_f;
        case 2: return g_v_f;
        case 3: return g_ctx_f;
        default: return g_att_f;
    }
}

// ---------------------------------------------------------------------------
// WMMA HGEMM: C[M,N] (fp32) = A[M,K] * Bt[N,K]^T, A/Bt fp16 k-contiguous.
// 128x128x32 tile, 256 threads = 8 warps (2 along M x 4 along N),
// warp tile 64x32 = 4x2 wmma 16x16x16 fragments, fp32 accumulate.
// Double-buffered smem via __pipeline_memcpy_async; rows padded to 40 halves.
//   CSKIP : causal tile skip (blocks fully above the diagonal exit)
//   KLIM  : K loop limited to row0+128 (A is exact zero beyond)
// Dims multiples of 128; K multiple of 32.
// ---------------------------------------------------------------------------
#define TBM 128
#define TBN 128
#define TBK 32
#define TPAD 40

template <bool CSKIP, bool KLIM>
__global__ void __launch_bounds__(256, 2)
hgemm_kernel(int aId, int bId, int cId, float* extC,
             int M, int N, int K,
             long long strA, long long strB, long long strC)
{
    const int row0 = blockIdx.y * TBM;
    const int col0 = blockIdx.x * TBN;
    if (CSKIP && col0 > row0 + TBM - 1) return;

    int Keff = K;
    if (KLIM) {
        int lim = row0 + TBM;
        if (lim < K) Keff = lim;
    }

    const long long bz = blockIdx.z;
    const __half* Ap = hbuf(aId) + bz * strA + (long long)row0 * K;
    const __half* Bp = hbuf(bId) + bz * strB + (long long)col0 * K;
    float* Cbase = (cId < 0) ? extC : fbuf(cId);
    float* Cp = Cbase + bz * strC;

    __shared__ __half sA[2][TBM * TPAD];
    __shared__ __half sB[2][TBN * TPAD];

    const int tid  = threadIdx.x;
    const int warp = tid >> 5;
    const int wm   = warp & 1;    // 0..1 : 64-row strip
    const int wn   = warp >> 1;   // 0..3 : 32-col strip

    const int ldR = tid >> 1;         // 0..127
    const int ldC = (tid & 1) * 8;    // 0 or 8 (halves)

    wmma::fragment<wmma::accumulator, 16, 16, 16, float> acc[4][2];
#pragma unroll
    for (int i = 0; i < 4; i++) {
#pragma unroll
        for (int j = 0; j < 2; j++) {
            wmma::fill_fragment(acc[i][j], 0.0f);
        }
    }

    const int iters = Keff / TBK;

    // preload stage 0
#pragma unroll
    for (int p = 0; p < 2; p++) {
        __pipeline_memcpy_async(&sA[0][ldR * TPAD + ldC + p * 16],
                                Ap + (long long)ldR * K + ldC + p * 16, 16);
        __pipeline_memcpy_async(&sB[0][ldR * TPAD + ldC + p * 16],
                                Bp + (long long)ldR * K + ldC + p * 16, 16);
    }
    __pipeline_commit();

    for (int it = 0; it < iters; ++it) {
        const int cur = it & 1;
        const int nxt = cur ^ 1;
        if (it + 1 < iters) {
            const int k0 = (it + 1) * TBK;
#pragma unroll
            for (int p = 0; p < 2; p++) {
                __pipeline_memcpy_async(&sA[nxt][ldR * TPAD + ldC + p * 16],
                                        Ap + (long long)ldR * K + k0 + ldC + p * 16, 16);
                __pipeline_memcpy_async(&sB[nxt][ldR * TPAD + ldC + p * 16],
                                        Bp + (long long)ldR * K + k0 + ldC + p * 16, 16);
            }
        }
        __pipeline_commit();
        __pipeline_wait_prior(1);
        __syncthreads();

#pragma unroll
        for (int kk = 0; kk < TBK; kk += 16) {
            wmma::fragment<wmma::matrix_a, 16, 16, 16, __half, wmma::row_major> af[4];
            wmma::fragment<wmma::matrix_b, 16, 16, 16, __half, wmma::col_major> bf[2];
#pragma unroll
            for (int mf = 0; mf < 4; mf++) {
                wmma::load_matrix_sync(af[mf], &sA[cur][(wm * 64 + mf * 16) * TPAD + kk], TPAD);
            }
#pragma unroll
            for (int nf = 0; nf < 2; nf++) {
                wmma::load_matrix_sync(bf[nf], &sB[cur][(wn * 32 + nf * 16) * TPAD + kk], TPAD);
            }
#pragma unroll
            for (int mf = 0; mf < 4; mf++) {
#pragma unroll
                for (int nf = 0; nf < 2; nf++) {
                    wmma::mma_sync(acc[mf][nf], af[mf], bf[nf], acc[mf][nf]);
                }
            }
        }
        __syncthreads();
    }

    // epilogue: direct fp32 store
#pragma unroll
    for (int mf = 0; mf < 4; mf++) {
#pragma unroll
        for (int nf = 0; nf < 2; nf++) {
            int r0 = row0 + wm * 64 + mf * 16;
            int c0 = col0 + wn * 32 + nf * 16;
            wmma::store_matrix_sync(&Cp[(long long)r0 * N + c0], acc[mf][nf], N, wmma::mem_row_major);
        }
    }
}

// ---------------------------------------------------------------------------
// conversions / transposes
// ---------------------------------------------------------------------------
__global__ void conv_inp_kernel(const float* __restrict__ in)
{
    long long i = ((long long)blockIdx.x * 256 + threadIdx.x) * 4;
    if (i < QKV_E) {
        float4 v = *reinterpret_cast<const float4*>(in + i);
        __half2* o = reinterpret_cast<__half2*>(g_inp_h + i);
        o[0] = __floats2half2_rn(v.x, v.y);
        o[1] = __floats2half2_rn(v.z, v.w);
    }
}

__global__ void conv_i_kernel(int srcId, int dstId)
{
    const float* in = fbuf(srcId);
    __half* out = hbuf(dstId);
    long long i = ((long long)blockIdx.x * 256 + threadIdx.x) * 4;
    if (i < QKV_E) {
        float4 v = *reinterpret_cast<const float4*>(in + i);
        __half2* o = reinterpret_cast<__half2*>(out + i);
        o[0] = __floats2half2_rn(v.x, v.y);
        o[1] = __floats2half2_rn(v.z, v.w);
    }
}

// weight transpose fp32 [D,D] -> fp16 transposed [D,D]; block (32,8)
__global__ void wtrans_kernel(const float* __restrict__ in, int dstId)
{
    __shared__ float t[32][33];
    __half* out = hbuf(dstId);
    int r0 = blockIdx.y * 32;
    int c0 = blockIdx.x * 32;
    for (int i = threadIdx.y; i < 32; i += 8) {
        t[i][threadIdx.x] = in[(long long)(r0 + i) * Dd + c0 + threadIdx.x];
    }
    __syncthreads();
    for (int i = threadIdx.y; i < 32; i += 8) {
        out[(long long)(c0 + i) * Dd + r0 + threadIdx.x] = __float2half(t[threadIdx.x][i]);
    }
}

// batched v transpose: g_v_f [B][S][D] fp32 -> g_vT_h [B][D][S] fp16
__global__ void vtrans_kernel()
{
    __shared__ float t[32][33];
    long long z = (long long)blockIdx.z * Ss * Dd;
    int r0 = blockIdx.y * 32;   // over S
    int c0 = blockIdx.x * 32;   // over D
    for (int i = threadIdx.y; i < 32; i += 8) {
        t[i][threadIdx.x] = g_v_f[z + (long long)(r0 + i) * Dd + c0 + threadIdx.x];
    }
    __syncthreads();
    for (int i = threadIdx.y; i < 32; i += 8) {
        g_vT_h[z + (long long)(c0 + i) * Ss + r0 + threadIdx.x] = __float2half(t[threadIdx.x][i]);
    }
}

// bias add on final fp32 output: out[r][c] += bo[c]
__global__ void bias_kernel(float* __restrict__ out, const float* __restrict__ bo)
{
    long long i = ((long long)blockIdx.x * 256 + threadIdx.x) * 4;
    if (i < QKV_E) {
        float4 v = *reinterpret_cast<float4*>(out + i);
        int c = (int)(i & (Dd - 1));
        v.x += bo[c];
        v.y += bo[c + 1];
        v.z += bo[c + 2];
        v.w += bo[c + 3];
        *reinterpret_cast<float4*>(out + i) = v;
    }
}

// ---------------------------------------------------------------------------
// Causal softmax: g_att_f fp32 -> g_att_h fp16. Mask j>q, scale 1/32,
// normalize; zero-fill tail of the row's own 128-block for the KLIM GEMM.
// ---------------------------------------------------------------------------
__global__ void __launch_bounds__(256)
softmax_kernel()
{
    const int q = blockIdx.x;
    const int b = blockIdx.y;
    const long long off = ((long long)b * Ss + q) * (long long)Ss;
    const float* row = g_att_f + off;
    __half* rowh = g_att_h + off;
    const int n = q + 1;
    const float scale = 0.03125f;   // 1/sqrt(1024)
    const int tid = threadIdx.x;

    __shared__ float sred[8];

    float m = -CUDART_INF_F;
    for (int j = tid; j < n; j += 256) {
        m = fmaxf(m, row[j] * scale);
    }
    for (int o = 16; o; o >>= 1) {
        m = fmaxf(m, __shfl_xor_sync(0xffffffffu, m, o));
    }
    if ((tid & 31) == 0) sred[tid >> 5] = m;
    __syncthreads();
    if (tid == 0) {
        float v = sred[0];
        for (int w = 1; w < 8; w++) v = fmaxf(v, sred[w]);
        sred[0] = v;
    }
    __syncthreads();
    m = sred[0];
    __syncthreads();

    float ev[8];
    float s = 0.0f;
    int cnt = 0;
    for (int j = tid; j < n; j += 256) {
        float e = __expf(row[j] * scale - m);
        ev[cnt] = e;
        cnt = cnt + 1;
        s += e;
    }
    for (int o = 16; o; o >>= 1) {
        s += __shfl_xor_sync(0xffffffffu, s, o);
    }
    if ((tid & 31) == 0) sred[tid >> 5] = s;
    __syncthreads();
    if (tid == 0) {
        float v = sred[0];
        for (int w = 1; w < 8; w++) v += sred[w];
        sred[0] = v;
    }
    __syncthreads();
    const float inv = 1.0f / sred[0];

    cnt = 0;
    for (int j = tid; j < n; j += 256) {
        rowh[j] = __float2half(ev[cnt] * inv);
        cnt = cnt + 1;
    }

    const int jend = ((q >> 7) + 1) << 7;
    for (int j = n + tid; j < jend; j += 256) {
        rowh[j] = __float2half(0.0f);
    }
}

// ---------------------------------------------------------------------------
extern "C" void kernel_launch(void* const* d_in, const int* in_sizes, int n_in,
                              void* d_out, int out_size)
{
    const float* inp = (const float*)d_in[0];
    const float* Wq  = (const float*)d_in[1];
    const float* Wk  = (const float*)d_in[2];
    const float* Wv  = (const float*)d_in[3];
    const float* Wo  = (const float*)d_in[4];
    const float* bo  = (const float*)d_in[5];
    float* out = (float*)d_out;

    const int M = Bb * Ss;                      // 8192
    const long long sQK = (long long)Ss * Dd;   // per-batch q/k/v stride
    const long long sAT = (long long)Ss * Ss;   // per-batch attn stride

    const unsigned nConv = (unsigned)((QKV_E / 4 + 255) / 256);
    dim3 tb(32, 8);
    dim3 tw(Dd / 32, Dd / 32);

    // fp32 -> fp16 input; weights -> fp16 transposed
    conv_inp_kernel<<<nConv, 256>>>(inp);
    wtrans_kernel<<<tw, tb>>>(Wq, 1);
    wtrans_kernel<<<tw, tb>>>(Wk, 2);
    wtrans_kernel<<<tw, tb>>>(Wv, 3);
    wtrans_kernel<<<tw, tb>>>(Wo, 4);

    // 1) Q/K/V projections (fp32 out)
    dim3 gProj(Dd / TBN, M / TBM, 1);
    hgemm_kernel<false, false><<<gProj, 256>>>(0, 1, 0, (float*)0, M, Dd, Dd, 0, 0, 0);
    hgemm_kernel<false, false><<<gProj, 256>>>(0, 2, 1, (float*)0, M, Dd, Dd, 0, 0, 0);
    hgemm_kernel<false, false><<<gProj, 256>>>(0, 3, 2, (float*)0, M, Dd, Dd, 0, 0, 0);

    // fp16 versions of q, k; transposed fp16 v
    conv_i_kernel<<<nConv, 256>>>(0, 5);
    conv_i_kernel<<<nConv, 256>>>(1, 6);
    dim3 gV(Dd / 32, Ss / 32, Bb);
    vtrans_kernel<<<gV, tb>>>();

    // 2) scores = Q * K^T per batch (causal tile skip), fp32 out
    dim3 gScore(Ss / TBN, Ss / TBM, Bb);
    hgemm_kernel<true, false><<<gScore, 256>>>(5, 6, 4, (float*)0, Ss, Ss, Dd, sQK, sQK, sAT);

    // 3) causal softmax -> fp16 probs
    dim3 gSm(Ss, Bb);
    softmax_kernel<<<gSm, 256>>>();

    // 4) ctx = attn * V per batch (K limited), fp32 out
    dim3 gCtx(Dd / TBN, Ss / TBM, Bb);
    hgemm_kernel<false, true><<<gCtx, 256>>>(8, 7, 3, (float*)0, Ss, Dd, Ss, sAT, sQK, sQK);

    // fp16 ctx
    conv_i_kernel<<<nConv, 256>>>(3, 9);

    // 5) out = ctx * W_o (fp32 out), then + b_o
    hgemm_kernel<false, false><<<gProj, 256>>>(9, 4, -1, out, M, Dd, Dd, 0, 0, 0);
    bias_kernel<<<nConv, 256>>>(out, bo);
}